// round 8
// baseline (speedup 1.0000x reference)
#include <cuda_runtime.h>

#define NN 1024
#define BB 128

// energy[b] = 0.5 * sum_{i<=j} W_ij * (1 + u_bi * u_bj),  u = 2v - 1.
// Grid (16,16,2): 64x64 W tiles (upper triangle) x 2 batch-groups of 64.
// Smem: Ws + one padded Uj tile only (33.0 KB -> 3 CTAs/SM @ 100KB carveout).
// Epilogue u_i values live in registers (contiguous 64B LDG.128 per thread).
__global__ __launch_bounds__(256) void potts_kernel(const float* __restrict__ V,
                                                    const float* __restrict__ W,
                                                    float* __restrict__ out) {
    __shared__ float Ws[64][64];     // 16384 B; float4 reads warp-uniform (broadcast)
    __shared__ float Uj[64][65];     // 16640 B; padded -> conflict-free, immediate-offset LDS
                                     // (reused as the ig-reduction buffer at the end)

    int ti = blockIdx.x, tj = blockIdx.y, bz = blockIdx.z;
    if (tj < ti) return;
    int i0 = ti * 64, j0 = tj * 64, b0 = bz * 64;
    int tid = threadIdx.x;
    bool diag = (ti == tj);

    int bb = tid & 63;   // batch lane (warp lanes = consecutive b)
    int ig = tid >> 6;   // i-group 0..3 (warp-uniform)

    // ---- Epilogue u_i values -> registers (issued first to overlap everything).
    // Per thread: V[(b0+bb)*NN + i0+ig*16 .. +15] is contiguous -> 4x LDG.128.
    float ui[16];
    {
        const float* vp = &V[(size_t)(b0 + bb) * NN + i0 + ig * 16];
        #pragma unroll
        for (int q = 0; q < 4; q++) {
            float4 v4 = *(const float4*)(vp + q * 4);
            ui[q * 4 + 0] = fmaf(2.0f, v4.x, -1.0f);
            ui[q * 4 + 1] = fmaf(2.0f, v4.y, -1.0f);
            ui[q * 4 + 2] = fmaf(2.0f, v4.z, -1.0f);
            ui[q * 4 + 3] = fmaf(2.0f, v4.w, -1.0f);
        }
    }

    // ---- W tile (coalesced float4), mask j<i on diagonal tiles ----
    {
        int r  = tid >> 4;          // 0..15
        int c4 = (tid & 15) << 2;   // 0,4,...,60
        #pragma unroll
        for (int rep = 0; rep < 4; rep++) {
            int row = r + rep * 16;
            float4 w = *(const float4*)&W[(size_t)(i0 + row) * NN + j0 + c4];
            if (diag) {
                if (c4 + 0 < row) w.x = 0.0f;
                if (c4 + 1 < row) w.y = 0.0f;
                if (c4 + 2 < row) w.z = 0.0f;
                if (c4 + 3 < row) w.w = 0.0f;
            }
            *(float4*)&Ws[row][c4] = w;
        }
    }
    // ---- Uj tile: Uj[j][b] = 2*V[b][j0+j]-1.
    // Writes: lanes vary j, bank=(j+b)%32 distinct. Reads: lanes vary b, distinct. ----
    {
        int j  = tid & 63;          // lane-consecutive -> coalesced gmem
        int bq = tid >> 6;          // 0..3
        #pragma unroll
        for (int rep = 0; rep < 16; rep++) {
            int b = bq + rep * 4;
            float vj = V[(size_t)(b0 + b) * NN + j0 + j];
            Uj[j][b] = fmaf(2.0f, vj, -1.0f);
        }
    }
    __syncthreads();

    // ---- Mainloop: acc[ii] = sum_j Ws[ig*16+ii][j] * u_{bb,j}.
    // Fully unrolled -> every LDS address is base + immediate (no per-load ALU).
    float acc[16];
    #pragma unroll
    for (int ii = 0; ii < 16; ii++) acc[ii] = 0.0f;

    #pragma unroll
    for (int j4 = 0; j4 < 64; j4 += 4) {
        float u0 = Uj[j4 + 0][bb];
        float u1 = Uj[j4 + 1][bb];
        float u2 = Uj[j4 + 2][bb];
        float u3 = Uj[j4 + 3][bb];
        #pragma unroll
        for (int ii = 0; ii < 16; ii++) {
            float4 w = *(const float4*)&Ws[ig * 16 + ii][j4];
            float a = acc[ii];
            a = fmaf(w.x, u0, a);
            a = fmaf(w.y, u1, a);
            a = fmaf(w.z, u2, a);
            a = fmaf(w.w, u3, a);
            acc[ii] = a;
        }
    }

    // ---- Tile row sums r_i -> Ws[i][0] (row i touched only by thread i) ----
    __syncthreads();
    if (tid < 64) {
        float rs = 0.0f;
        #pragma unroll 8
        for (int j = 0; j < 64; j++) {
            int jj = (j + tid) & 63;   // rotate -> conflict-free
            rs += Ws[tid][jj];
        }
        Ws[tid][0] = rs;
    }
    __syncthreads();

    // ---- Per-thread term: sum_i u_bi*Q_i(b) (its 16 rows) + its share of T0 ----
    float e = 0.0f, t0 = 0.0f;
    #pragma unroll
    for (int ii = 0; ii < 16; ii++) {
        int row = ig * 16 + ii;
        e  = fmaf(acc[ii], ui[ii], e);
        t0 += Ws[row][0];              // broadcast read
    }

    // ---- Reduce the 4 ig-groups per b in smem (Uj is dead), then 1 atomic/b ----
    float* red = &Uj[0][0];
    red[ig * 64 + bb] = e + t0;        // bank = bb%32, lanes distinct
    __syncthreads();
    if (tid < 64) {
        float s = red[tid] + red[64 + tid] + red[128 + tid] + red[192 + tid];
        atomicAdd(&out[b0 + tid], 0.5f * s);
    }
}

extern "C" void kernel_launch(void* const* d_in, const int* in_sizes, int n_in,
                              void* d_out, int out_size) {
    // Defensive input identification by element count.
    const float* V = (const float*)d_in[0];
    const float* W = (const float*)d_in[1];
    if (n_in >= 2 && in_sizes[0] == NN * NN && in_sizes[1] == BB * NN) {
        V = (const float*)d_in[1];
        W = (const float*)d_in[0];
    }
    float* out = (float*)d_out;               // [128] fp32

    cudaMemsetAsync(out, 0, sizeof(float) * BB);   // out is poisoned; we accumulate into it
    dim3 grid(16, 16, 2);
    potts_kernel<<<grid, 256>>>(V, W, out);
}

// round 10
// speedup vs baseline: 1.4251x; 1.4251x over previous
#include <cuda_runtime.h>

#define NN 1024
#define BB 128

// energy[b] = 0.5 * sum_{i<=j} W_ij * (1 + u_bi * u_bj),  u = 2v - 1.
// Grid (136, 4): 136 linearized upper-triangle 64x64 W tiles x 4 batch-groups of 32.
// 544 live blocks (~3.7 CTAs/SM -> occ ~45%), smem 32.9 KB/CTA.
// Thread (bb 0..31, ig 0..7): 8 i-rows x 1 batch column, acc in registers.
__global__ __launch_bounds__(256) void potts_kernel(const float* __restrict__ V,
                                                    const float* __restrict__ W,
                                                    float* __restrict__ out) {
    __shared__ float Ws[64][64];   // masked W tile [i][j]; float4 reads warp-uniform broadcast
    __shared__ float Uj[64][33];   // u tile (j-range): bank (j+b)%32 -> conflict-free both ways
    __shared__ float Ui[64][33];   // u tile (i-range), same layout

    // ---- Decode linear tile index -> (ti, tj) in upper triangle (16x16 tiles) ----
    int k = blockIdx.x;
    int ti = (int)((33.0f - sqrtf(1089.0f - 8.0f * (float)k)) * 0.5f);
    // exact fixup against fp error: start(t) = 16t - t(t-1)/2
    while (16 * (ti + 1) - ((ti + 1) * ti) / 2 <= k) ti++;
    while (16 * ti - (ti * (ti - 1)) / 2 > k) ti--;
    int tj = ti + (k - (16 * ti - (ti * (ti - 1)) / 2));

    int i0 = ti * 64, j0 = tj * 64, b0 = blockIdx.y * 32;
    int tid = threadIdx.x;
    bool diag = (ti == tj);

    // ---- Load W tile (coalesced float4), mask j<i on diagonal tiles ----
    {
        int r  = tid >> 4;          // 0..15
        int c4 = (tid & 15) << 2;   // 0,4,...,60
        #pragma unroll
        for (int rep = 0; rep < 4; rep++) {
            int row = r + rep * 16;
            float4 w = *(const float4*)&W[(size_t)(i0 + row) * NN + j0 + c4];
            if (diag) {
                if (c4 + 0 < row) w.x = 0.0f;
                if (c4 + 1 < row) w.y = 0.0f;
                if (c4 + 2 < row) w.z = 0.0f;
                if (c4 + 3 < row) w.w = 0.0f;
            }
            *(float4*)&Ws[row][c4] = w;
        }
    }
    // ---- Load u tiles: 64 j x 32 b each, coalesced gmem (lanes vary j) ----
    {
        int j  = tid & 63;
        int bq = tid >> 6;          // 0..3
        #pragma unroll
        for (int rep = 0; rep < 8; rep++) {
            int b = bq + rep * 4;   // 0..31
            float vj = V[(size_t)(b0 + b) * NN + j0 + j];
            Uj[j][b] = fmaf(2.0f, vj, -1.0f);
            float vi = V[(size_t)(b0 + b) * NN + i0 + j];
            Ui[j][b] = fmaf(2.0f, vi, -1.0f);
        }
    }
    __syncthreads();

    int bb = tid & 31;   // batch lane = lane id -> conflict-free u reads
    int ig = tid >> 5;   // i-group 0..7 (warp-uniform -> broadcast Ws reads)

    float acc[8];
    #pragma unroll
    for (int ii = 0; ii < 8; ii++) acc[ii] = 0.0f;

    #pragma unroll 4
    for (int j4 = 0; j4 < 64; j4 += 4) {
        float u0 = Uj[j4 + 0][bb];
        float u1 = Uj[j4 + 1][bb];
        float u2 = Uj[j4 + 2][bb];
        float u3 = Uj[j4 + 3][bb];
        #pragma unroll
        for (int ii = 0; ii < 8; ii++) {
            float4 w = *(const float4*)&Ws[ig * 8 + ii][j4];
            float a = acc[ii];
            a = fmaf(w.x, u0, a);
            a = fmaf(w.y, u1, a);
            a = fmaf(w.z, u2, a);
            a = fmaf(w.w, u3, a);
            acc[ii] = a;
        }
    }

    // ---- Tile row sums r_i -> Ws[i][0] (row i touched only by thread i) ----
    __syncthreads();
    if (tid < 64) {
        float rs = 0.0f;
        #pragma unroll 8
        for (int j = 0; j < 64; j++) {
            int jj = (j + tid) & 63;   // rotate -> conflict-free
            rs += Ws[tid][jj];
        }
        Ws[tid][0] = rs;
    }
    __syncthreads();

    // ---- Per-thread: sum over its 8 rows of u_bi*Q_i(b) + its share of T0 ----
    float e = 0.0f;
    #pragma unroll
    for (int ii = 0; ii < 8; ii++) {
        int row = ig * 8 + ii;
        e = fmaf(acc[ii], Ui[row][bb], e);
    }
    float t0 = 0.0f;
    #pragma unroll
    for (int ii = 0; ii < 8; ii++) t0 += Ws[ig * 8 + ii][0];   // broadcast reads

    // ---- Reduce 8 ig-groups per b in smem (Uj dead), then 1 atomic per b ----
    float* red = &Uj[0][0];            // 256 floats needed, 2112 available
    red[ig * 32 + bb] = e + t0;        // lanes bb -> distinct banks
    __syncthreads();
    if (tid < 32) {
        float s = 0.0f;
        #pragma unroll
        for (int g = 0; g < 8; g++) s += red[g * 32 + tid];
        atomicAdd(&out[b0 + tid], 0.5f * s);
    }
}

extern "C" void kernel_launch(void* const* d_in, const int* in_sizes, int n_in,
                              void* d_out, int out_size) {
    // Defensive input identification by element count.
    const float* V = (const float*)d_in[0];
    const float* W = (const float*)d_in[1];
    if (n_in >= 2 && in_sizes[0] == NN * NN && in_sizes[1] == BB * NN) {
        V = (const float*)d_in[1];
        W = (const float*)d_in[0];
    }
    float* out = (float*)d_out;               // [128] fp32

    cudaMemsetAsync(out, 0, sizeof(float) * BB);   // out is poisoned; we accumulate into it
    dim3 grid(136, 4);                             // 136 upper-triangle tiles x 4 b-groups
    potts_kernel<<<grid, 256>>>(V, W, out);
}